// round 13
// baseline (speedup 1.0000x reference)
#include <cuda_runtime.h>
#include <cuda_bf16.h>
#include <cstdint>

#define BATCH 2
#define SEQ   2048
#define DIM   1024
#define NH    16
#define HW    64
#define BHTOT (BATCH*NH)
#define MTOT  (BATCH*SEQ)

// ---------------- global scratch ----------------
__device__ __nv_bfloat16 g_xh[MTOT*DIM];
__device__ __nv_bfloat16 g_wh[3*DIM*DIM];
__device__ __nv_bfloat16 g_qb[BHTOT*SEQ*HW];
__device__ __nv_bfloat16 g_kb[BHTOT*SEQ*HW];
__device__ __nv_bfloat16 g_vb[BHTOT*SEQ*HW];
__device__ float         g_sx[BATCH*DIM];
__device__ float         g_colsum[BHTOT*HW];

// ---------------- helpers ---------------------------------------------------
__device__ __forceinline__ uint32_t smem_u32(const void* p) {
    uint32_t a;
    asm("{ .reg .u64 t; cvta.to.shared.u64 t, %1; cvt.u32.u64 %0, t; }"
        : "=r"(a) : "l"(p));
    return a;
}
__device__ __forceinline__ void ldsm_x4(uint32_t (&r)[4], uint32_t addr) {
    asm volatile("ldmatrix.sync.aligned.m8n8.x4.shared.b16 {%0,%1,%2,%3}, [%4];"
                 : "=r"(r[0]), "=r"(r[1]), "=r"(r[2]), "=r"(r[3]) : "r"(addr));
}
__device__ __forceinline__ void ldsm_x2(uint32_t (&r)[2], uint32_t addr) {
    asm volatile("ldmatrix.sync.aligned.m8n8.x2.shared.b16 {%0,%1}, [%2];"
                 : "=r"(r[0]), "=r"(r[1]) : "r"(addr));
}
__device__ __forceinline__ void ldsm_x2t(uint32_t (&r)[2], uint32_t addr) {
    asm volatile("ldmatrix.sync.aligned.m8n8.x2.trans.shared.b16 {%0,%1}, [%2];"
                 : "=r"(r[0]), "=r"(r[1]) : "r"(addr));
}
__device__ __forceinline__ void mma_bf16(float (&d)[4], const uint32_t (&a)[4],
                                         const uint32_t (&b)[2]) {
    asm volatile("mma.sync.aligned.m16n8k16.row.col.f32.bf16.bf16.f32 "
                 "{%0,%1,%2,%3}, {%4,%5,%6,%7}, {%8,%9}, {%0,%1,%2,%3};"
                 : "+f"(d[0]), "+f"(d[1]), "+f"(d[2]), "+f"(d[3])
                 : "r"(a[0]), "r"(a[1]), "r"(a[2]), "r"(a[3]),
                   "r"(b[0]), "r"(b[1]));
}
#define CP16(dst, src) \
    asm volatile("cp.async.cg.shared.global [%0], [%1], 16;" \
                 :: "r"(dst), "l"(src))
#define CP_COMMIT() asm volatile("cp.async.commit_group;" ::: "memory")
#define CP_WAIT(n)  asm volatile("cp.async.wait_group %0;" :: "n"(n) : "memory")

__device__ __forceinline__ float fexp(float x) {
    const float L = 1.4426950408889634f;
    float t = fmaf(x, L, 12582912.0f);
    float n = t - 12582912.0f;
    float r = fmaf(x, L, -n);
    float u = r * 0.6931471805599453f;
    float p = 1.3888889e-3f;
    p = fmaf(p, u, 8.3333333e-3f);
    p = fmaf(p, u, 4.1666667e-2f);
    p = fmaf(p, u, 1.6666667e-1f);
    p = fmaf(p, u, 5.0e-1f);
    p = fmaf(p, u, 1.0f);
    p = fmaf(p, u, 1.0f);
    int e = (int)n;
    return __int_as_float((e + 127) << 23) * p;
}
__device__ __forceinline__ uint32_t pack_bf16x2(float a, float b) {
    __nv_bfloat162 pk = __floats2bfloat162_rn(a, b);
    return *(uint32_t*)&pk;
}

// ======================= bf16 casts =========================================
__global__ __launch_bounds__(256) void split_x_kernel(const float* __restrict__ x)
{
    int i = (blockIdx.x * 256 + threadIdx.x) * 4;
    float4 v = *(const float4*)(x + i);
    __nv_bfloat16 h[4] = {
        __float2bfloat16(v.x), __float2bfloat16(v.y),
        __float2bfloat16(v.z), __float2bfloat16(v.w) };
    *(uint64_t*)&g_xh[i] = *(const uint64_t*)h;
}

__global__ __launch_bounds__(256) void split_w_kernel(
    const float* __restrict__ Wq, const float* __restrict__ Wk,
    const float* __restrict__ Wv)
{
    const int z = blockIdx.y;
    const float* W = (z == 0) ? Wq : (z == 1) ? Wk : Wv;
    int i = (blockIdx.x * 256 + threadIdx.x) * 4;
    float4 v = *(const float4*)(W + i);
    __nv_bfloat16 h[4] = {
        __float2bfloat16(v.x), __float2bfloat16(v.y),
        __float2bfloat16(v.z), __float2bfloat16(v.w) };
    *(uint64_t*)&g_wh[(size_t)z * DIM * DIM + i] = *(const uint64_t*)h;
}

// ======================= exact colsum via rank-1 identity ===================
__global__ __launch_bounds__(256) void sumx_kernel(const float* __restrict__ x)
{
    const int d = blockIdx.x * 256 + threadIdx.x;
    const int b = blockIdx.y;
    const float* xp = x + (size_t)b * SEQ * DIM + d;
    float s0 = 0, s1 = 0, s2 = 0, s3 = 0;
    for (int s = 0; s < SEQ; s += 4) {
        s0 += xp[(size_t)(s + 0) * DIM];
        s1 += xp[(size_t)(s + 1) * DIM];
        s2 += xp[(size_t)(s + 2) * DIM];
        s3 += xp[(size_t)(s + 3) * DIM];
    }
    g_sx[b * DIM + d] = (s0 + s1) + (s2 + s3);
}

__global__ __launch_bounds__(256) void colsumv_kernel(
    const float* __restrict__ Wv, const float* __restrict__ bv)
{
    const int wid  = threadIdx.x >> 5;
    const int lane = threadIdx.x & 31;
    const int gw   = blockIdx.x * 8 + wid;
    const int n    = gw & (DIM - 1);
    const int b    = gw >> 10;
    const float* wr = Wv + (size_t)n * DIM;
    const float* sx = g_sx + b * DIM;
    float acc = 0.0f;
#pragma unroll
    for (int it = 0; it < 8; it++) {
        int j = (it * 32 + lane) * 4;
        float4 w4 = *(const float4*)(wr + j);
        float4 s4 = *(const float4*)(sx + j);
        acc += w4.x * s4.x + w4.y * s4.y + w4.z * s4.z + w4.w * s4.w;
    }
#pragma unroll
    for (int o = 16; o > 0; o >>= 1)
        acc += __shfl_xor_sync(0xffffffffu, acc, o);
    if (lane == 0) {
        int h = n >> 6, w = n & 63;
        g_colsum[(b * NH + h) * HW + w] = acc + 2048.0f * bv[n];
    }
}

// ======================= QKV projection: 128x128 tiles, cp.async ============
#define ASTR 40

__global__ __launch_bounds__(256) void qkv_kernel(
    const float* __restrict__ bq, const float* __restrict__ bk,
    const float* __restrict__ bv)
{
    __shared__ __align__(16) unsigned short sA[2][128*ASTR];
    __shared__ __align__(16) unsigned short sB[2][128*ASTR];
    __shared__ float s_bias[128];

    const int t    = threadIdx.x;
    const int wid  = t >> 5;
    const int lane = t & 31;
    const int z    = blockIdx.z;
    const int n0   = blockIdx.x * 128;
    const int m0   = blockIdx.y * 128;

    const __nv_bfloat16* wofs = g_wh + (size_t)z * DIM * DIM;

    if (t < 128) {
        const float* bias = (z == 0) ? bq : (z == 1) ? bk : bv;
        s_bias[t] = bias[n0 + t];
    }

    const int wm = wid & 3;
    const int wn = wid >> 2;
    const int arow = t >> 2, aseg = t & 3;

    float d[2][8][4];
#pragma unroll
    for (int i = 0; i < 2; i++)
#pragma unroll
        for (int nf = 0; nf < 8; nf++)
#pragma unroll
            for (int r = 0; r < 4; r++) d[i][nf][r] = 0.0f;

#pragma unroll
    for (int i = 0; i < 2; i++) {
        int row = arow + i * 64;
        CP16(smem_u32(&sA[0][row * ASTR + aseg * 8]),
             &g_xh[(size_t)(m0 + row) * DIM + aseg * 8]);
        CP16(smem_u32(&sB[0][row * ASTR + aseg * 8]),
             &wofs[(size_t)(n0 + row) * DIM + aseg * 8]);
    }
    CP_COMMIT();

    for (int kc = 0; kc < 32; kc++) {
        if (kc < 31) {
            const int k0n = (kc + 1) * 32;
            const int bn  = (kc + 1) & 1;
#pragma unroll
            for (int i = 0; i < 2; i++) {
                int row = arow + i * 64;
                CP16(smem_u32(&sA[bn][row * ASTR + aseg * 8]),
                     &g_xh[(size_t)(m0 + row) * DIM + k0n + aseg * 8]);
                CP16(smem_u32(&sB[bn][row * ASTR + aseg * 8]),
                     &wofs[(size_t)(n0 + row) * DIM + k0n + aseg * 8]);
            }
            CP_COMMIT();
            CP_WAIT(1);
        } else {
            CP_WAIT(0);
        }
        __syncthreads();

        const uint32_t au = smem_u32(sA[kc & 1]);
        const uint32_t bu = smem_u32(sB[kc & 1]);
#pragma unroll
        for (int ks = 0; ks < 2; ks++) {
            uint32_t ah0[4], ah1[4];
            ldsm_x4(ah0, au + ((wm * 32 + (lane & 15)) * ASTR
                               + ks * 16 + (lane >> 4) * 8) * 2);
            ldsm_x4(ah1, au + ((wm * 32 + 16 + (lane & 15)) * ASTR
                               + ks * 16 + (lane >> 4) * 8) * 2);
#pragma unroll
            for (int nf = 0; nf < 8; nf++) {
                uint32_t b[2];
                ldsm_x2(b, bu + ((wn * 64 + nf * 8 + (lane & 7)) * ASTR
                                 + ks * 16 + (lane & 8)) * 2);
                mma_bf16(d[0][nf], ah0, b);
                mma_bf16(d[1][nf], ah1, b);
            }
        }
        __syncthreads();
    }

    const int h = (n0 >> 6) + wn;
    __nv_bfloat16* outp = (z == 0) ? g_qb : (z == 1) ? g_kb : g_vb;
#pragma unroll
    for (int i = 0; i < 2; i++) {
        int r = m0 + wm * 32 + i * 16 + (lane >> 2);
#pragma unroll
        for (int nf = 0; nf < 8; nf++) {
            int cl = nf * 8 + 2 * (lane & 3);
            float b0 = s_bias[wn * 64 + cl];
            float b1 = s_bias[wn * 64 + cl + 1];
            float v0 = d[i][nf][0] + b0;
            float v1 = d[i][nf][1] + b1;
            float v2 = d[i][nf][2] + b0;
            float v3 = d[i][nf][3] + b1;
#pragma unroll
            for (int half = 0; half < 2; half++) {
                int rr = r + half * 8;
                int b = rr >> 11, s = rr & (SEQ - 1);
                size_t o = ((size_t)((b * NH + h) * SEQ + s)) * HW + cl;
                *(__nv_bfloat162*)&outp[o] =
                    __floats2bfloat162_rn(half ? v2 : v0, half ? v3 : v1);
            }
        }
    }
}

// ===== single-pass fused attention: register-resident e/e^2 (FA2 repack) ====
// h = (colsum + M1/z + M2/(2z^2)) / (2049 + s2/(2z^2))
#define KVSTR   72
#define KVBYTES (128*KVSTR*2)
#define OFF_K    0
#define OFF_V    (2*KVBYTES)              // 36864
#define OFF_Q    (4*KVBYTES)              // 73728
#define OFF_CS   (OFF_Q + 32*KVSTR*2)     // 78336
#define OFF_Z    (OFF_CS + 256)           // 78592
#define OFF_S2   (OFF_Z + 128)            // 78720
#define ATTN_SMEM (OFF_S2 + 128)          // 78848

__global__ __launch_bounds__(256, 2) void attn_kernel(float* __restrict__ out)
{
    extern __shared__ char dsm[];
    char*  k_p  = dsm + OFF_K;
    char*  v_p  = dsm + OFF_V;
    char*  q_p  = dsm + OFF_Q;
    float* s_cs = (float*)(dsm + OFF_CS);
    float* s_z  = (float*)(dsm + OFF_Z);
    float* s_s2 = (float*)(dsm + OFF_S2);

    const uint32_t k_u = smem_u32(k_p);
    const uint32_t v_u = smem_u32(v_p);
    const uint32_t q_u = smem_u32(q_p);

    const int t    = threadIdx.x;
    const int wid  = t >> 5;          // 8 warps
    const int lane = t & 31;
    const int q0   = blockIdx.x * 32;
    const int bh   = blockIdx.y;

    const __nv_bfloat16* qg = g_qb + ((size_t)bh * SEQ + q0) * HW;
    const __nv_bfloat16* kg = g_kb + (size_t)bh * SEQ * HW;
    const __nv_bfloat16* vg = g_vb + (size_t)bh * SEQ * HW;

    const int wm   = wid & 1;         // 16-row half
    const int wq   = wid >> 1;        // 0..3: key 32-slice within chunk
    const int wm16 = wm * 16;
    const int erow = wm16 + (lane >> 2);

    if (t < 32) { s_z[t] = 0.0f; s_s2[t] = 0.0f; }
    if (t < 64) s_cs[t] = g_colsum[bh * HW + t];
    {   // Q tile 32x64
        int row = t >> 3, seg = t & 7;
        *(uint4*)(q_p + (row * KVSTR + seg * 8) * 2) =
            *(const uint4*)(qg + row * HW + seg * 8);
    }
    // prologue: K0 + V0
#pragma unroll
    for (int i = 0; i < 4; i++) {
        int idx = t + i * 256;
        int row = idx >> 3, seg = idx & 7;
        CP16(k_u + (row * KVSTR + seg * 8) * 2, kg + row * HW + seg * 8);
        CP16(v_u + (row * KVSTR + seg * 8) * 2, vg + row * HW + seg * 8);
    }
    CP_COMMIT();
    __syncthreads();

    uint32_t aq[4][4];
#pragma unroll
    for (int ks = 0; ks < 4; ks++) {
        uint32_t off = ((wm16 + (lane & 15)) * KVSTR + ks * 16 + (lane >> 4) * 8) * 2;
        ldsm_x4(aq[ks], q_u + off);
    }

    float zp0 = 0.f, zp1 = 0.f, sp0 = 0.f, sp1 = 0.f;
    float dd[8][4], dd2[8][4];
#pragma unroll
    for (int nf = 0; nf < 8; nf++)
#pragma unroll
        for (int r = 0; r < 4; r++) { dd[nf][r] = 0.0f; dd2[nf][r] = 0.0f; }

    for (int c = 0; c < 16; c++) {
        if (c < 15) {
            const __nv_bfloat16* ksrc = kg + (size_t)(c + 1) * 128 * HW;
            const __nv_bfloat16* vsrc = vg + (size_t)(c + 1) * 128 * HW;
            uint32_t kdst = k_u + ((c + 1) & 1) * KVBYTES;
            uint32_t vdst = v_u + ((c + 1) & 1) * KVBYTES;
#pragma unroll
            for (int i = 0; i < 4; i++) {
                int idx = t + i * 256;
                int row = idx >> 3, seg = idx & 7;
                CP16(kdst + (row * KVSTR + seg * 8) * 2, ksrc + row * HW + seg * 8);
                CP16(vdst + (row * KVSTR + seg * 8) * 2, vsrc + row * HW + seg * 8);
            }
            CP_COMMIT();
            CP_WAIT(1);
        } else {
            CP_WAIT(0);
        }
        __syncthreads();

        const uint32_t kbuf = k_u + (c & 1) * KVBYTES;
        const uint32_t vbuf = v_u + (c & 1) * KVBYTES;

#pragma unroll
        for (int j = 0; j < 2; j++) {       // two k16 key blocks per warp
            uint32_t ae[4], ae2[4];
#pragma unroll
            for (int hh = 0; hh < 2; hh++) {
                const int nf = j * 2 + hh;  // n8 block within warp's 32 keys
                float d[4] = {0, 0, 0, 0};
#pragma unroll
                for (int ks = 0; ks < 4; ks++) {
                    uint32_t b[2];
                    uint32_t off = ((wq * 32 + nf * 8 + (lane & 7)) * KVSTR
                                    + ks * 16 + (lane & 8)) * 2;
                    ldsm_x2(b, kbuf + off);
                    mma_bf16(d, aq[ks], b);
                }
                float e0 = fexp(d[0] * 0.125f);
                float e1 = fexp(d[1] * 0.125f);
                float e2 = fexp(d[2] * 0.125f);
                float e3 = fexp(d[3] * 0.125f);
                zp0 += e0 + e1;  zp1 += e2 + e3;
                float g0 = e0 * e0, g1 = e1 * e1, g2 = e2 * e2, g3 = e3 * e3;
                sp0 += g0 + g1;  sp1 += g2 + g3;
                // c-frag -> a-frag repack (FA2): a0=pack(c0,c1), a1=pack(c2,c3)
                ae[hh * 2]      = pack_bf16x2(e0, e1);
                ae[hh * 2 + 1]  = pack_bf16x2(e2, e3);
                ae2[hh * 2]     = pack_bf16x2(g0, g1);
                ae2[hh * 2 + 1] = pack_bf16x2(g2, g3);
            }
            // PV: keys [wq*32 + j*16, +16), both moments share V b-frags
#pragma unroll
            for (int nf = 0; nf < 8; nf++) {
                uint32_t b[2];
                uint32_t boff = ((wq * 32 + j * 16 + (lane & 7) + (lane & 8)) * KVSTR
                                 + nf * 8) * 2;
                ldsm_x2t(b, vbuf + boff);
                mma_bf16(dd[nf],  ae,  b);
                mma_bf16(dd2[nf], ae2, b);
            }
        }
    }

    // row sums: reduce lanes sharing a row, then across wq warps via atomics
    zp0 += __shfl_xor_sync(0xffffffffu, zp0, 1);
    zp0 += __shfl_xor_sync(0xffffffffu, zp0, 2);
    zp1 += __shfl_xor_sync(0xffffffffu, zp1, 1);
    zp1 += __shfl_xor_sync(0xffffffffu, zp1, 2);
    sp0 += __shfl_xor_sync(0xffffffffu, sp0, 1);
    sp0 += __shfl_xor_sync(0xffffffffu, sp0, 2);
    sp1 += __shfl_xor_sync(0xffffffffu, sp1, 1);
    sp1 += __shfl_xor_sync(0xffffffffu, sp1, 2);
    if ((lane & 3) == 0) {
        atomicAdd(&s_z[erow],      zp0);
        atomicAdd(&s_z[erow + 8],  zp1);
        atomicAdd(&s_s2[erow],     sp0);
        atomicAdd(&s_s2[erow + 8], sp1);
    }

    // reuse K/V smem region for M1/M2 cross-wq reduction (32x64 fp32 each)
    float* M1 = (float*)dsm;
    float* M2 = (float*)(dsm + 8192);
    __syncthreads();
    for (int i = t; i < 4096; i += 256) ((float*)dsm)[i] = 0.0f;
    __syncthreads();
    {
#pragma unroll
        for (int nf = 0; nf < 8; nf++) {
            int col = nf * 8 + 2 * (lane & 3);
            atomicAdd(&M1[erow * 64 + col],           dd[nf][0]);
            atomicAdd(&M1[erow * 64 + col + 1],       dd[nf][1]);
            atomicAdd(&M1[(erow + 8) * 64 + col],     dd[nf][2]);
            atomicAdd(&M1[(erow + 8) * 64 + col + 1], dd[nf][3]);
            atomicAdd(&M2[erow * 64 + col],           dd2[nf][0]);
            atomicAdd(&M2[erow * 64 + col + 1],       dd2[nf][1]);
            atomicAdd(&M2[(erow + 8) * 64 + col],     dd2[nf][2]);
            atomicAdd(&M2[(erow + 8) * 64 + col + 1], dd2[nf][3]);
        }
    }
    __syncthreads();

    // epilogue: 256 threads cover 32 rows x 64 cols (8 floats each)
    {
        const int b  = bh >> 4, hh = bh & 15;
        const int row = t >> 3;
        const int c0  = (t & 7) * 8;
        float z    = s_z[row];
        float invz = 1.0f / z;
        float i2z2 = 0.5f * invz * invz;
        float den  = 1.0f / (2049.0f + s_s2[row] * i2z2);
        float* op = out + ((size_t)(b * SEQ + q0 + row)) * DIM + hh * HW + c0;
#pragma unroll
        for (int j = 0; j < 8; j += 4) {
            float4 m1 = *(const float4*)&M1[row * 64 + c0 + j];
            float4 m2 = *(const float4*)&M2[row * 64 + c0 + j];
            float4 cs = *(const float4*)&s_cs[c0 + j];
            float4 o;
            o.x = (cs.x + fmaf(m1.x, invz, m2.x * i2z2)) * den;
            o.y = (cs.y + fmaf(m1.y, invz, m2.y * i2z2)) * den;
            o.z = (cs.z + fmaf(m1.z, invz, m2.z * i2z2)) * den;
            o.w = (cs.w + fmaf(m1.w, invz, m2.w * i2z2)) * den;
            *(float4*)(op + j) = o;
        }
    }
}

// ---------------- launch -----------------------------------------------------
extern "C" void kernel_launch(void* const* d_in, const int* in_sizes, int n_in,
                              void* d_out, int out_size)
{
    const float* x  = (const float*)d_in[0];
    const float* Wq = (const float*)d_in[1];
    const float* bq = (const float*)d_in[2];
    const float* Wk = (const float*)d_in[3];
    const float* bk = (const float*)d_in[4];
    const float* Wv = (const float*)d_in[5];
    const float* bv = (const float*)d_in[6];
    float* out = (float*)d_out;

    split_x_kernel<<<MTOT * DIM / 1024, 256>>>(x);
    {
        dim3 gw(DIM * DIM / 1024, 3);
        split_w_kernel<<<gw, 256>>>(Wq, Wk, Wv);
    }
    {
        dim3 gs(DIM / 256, BATCH);
        sumx_kernel<<<gs, 256>>>(x);
    }
    colsumv_kernel<<<BATCH * DIM / 8, 256>>>(Wv, bv);
    {
        dim3 g(DIM / 128, MTOT / 128, 3);
        qkv_kernel<<<g, 256>>>(bq, bk, bv);
    }
    {
        cudaFuncSetAttribute(attn_kernel,
                             cudaFuncAttributeMaxDynamicSharedMemorySize, ATTN_SMEM);
        dim3 g2(SEQ / 32, BHTOT);
        attn_kernel<<<g2, 256, ATTN_SMEM>>>(out);
    }
}

// round 14
// speedup vs baseline: 1.2066x; 1.2066x over previous
#include <cuda_runtime.h>
#include <cuda_bf16.h>
#include <cstdint>

#define BATCH 2
#define SEQ   2048
#define DIM   1024
#define NH    16
#define HW    64
#define BHTOT (BATCH*NH)
#define MTOT  (BATCH*SEQ)

// ---------------- global scratch ----------------
__device__ __nv_bfloat16 g_xh[MTOT*DIM];
__device__ __nv_bfloat16 g_wh[3*DIM*DIM];
__device__ __nv_bfloat16 g_qb[BHTOT*SEQ*HW];
__device__ __nv_bfloat16 g_kb[BHTOT*SEQ*HW];
__device__ __nv_bfloat16 g_vb[BHTOT*SEQ*HW];
__device__ float         g_sx[BATCH*DIM];
__device__ float         g_colsum[BHTOT*HW];

// ---------------- helpers ---------------------------------------------------
__device__ __forceinline__ uint32_t smem_u32(const void* p) {
    uint32_t a;
    asm("{ .reg .u64 t; cvta.to.shared.u64 t, %1; cvt.u32.u64 %0, t; }"
        : "=r"(a) : "l"(p));
    return a;
}
__device__ __forceinline__ void ldsm_x4(uint32_t (&r)[4], uint32_t addr) {
    asm volatile("ldmatrix.sync.aligned.m8n8.x4.shared.b16 {%0,%1,%2,%3}, [%4];"
                 : "=r"(r[0]), "=r"(r[1]), "=r"(r[2]), "=r"(r[3]) : "r"(addr));
}
__device__ __forceinline__ void ldsm_x2(uint32_t (&r)[2], uint32_t addr) {
    asm volatile("ldmatrix.sync.aligned.m8n8.x2.shared.b16 {%0,%1}, [%2];"
                 : "=r"(r[0]), "=r"(r[1]) : "r"(addr));
}
__device__ __forceinline__ void ldsm_x4t(uint32_t (&r)[4], uint32_t addr) {
    asm volatile("ldmatrix.sync.aligned.m8n8.x4.trans.shared.b16 {%0,%1,%2,%3}, [%4];"
                 : "=r"(r[0]), "=r"(r[1]), "=r"(r[2]), "=r"(r[3]) : "r"(addr));
}
__device__ __forceinline__ void mma_bf16(float (&d)[4], const uint32_t (&a)[4],
                                         const uint32_t (&b)[2]) {
    asm volatile("mma.sync.aligned.m16n8k16.row.col.f32.bf16.bf16.f32 "
                 "{%0,%1,%2,%3}, {%4,%5,%6,%7}, {%8,%9}, {%0,%1,%2,%3};"
                 : "+f"(d[0]), "+f"(d[1]), "+f"(d[2]), "+f"(d[3])
                 : "r"(a[0]), "r"(a[1]), "r"(a[2]), "r"(a[3]),
                   "r"(b[0]), "r"(b[1]));
}
__device__ __forceinline__ void mma_bf16s(float (&d)[4], const uint32_t (&a)[4],
                                          uint32_t b0, uint32_t b1) {
    asm volatile("mma.sync.aligned.m16n8k16.row.col.f32.bf16.bf16.f32 "
                 "{%0,%1,%2,%3}, {%4,%5,%6,%7}, {%8,%9}, {%0,%1,%2,%3};"
                 : "+f"(d[0]), "+f"(d[1]), "+f"(d[2]), "+f"(d[3])
                 : "r"(a[0]), "r"(a[1]), "r"(a[2]), "r"(a[3]),
                   "r"(b0), "r"(b1));
}
#define CP16(dst, src) \
    asm volatile("cp.async.cg.shared.global [%0], [%1], 16;" \
                 :: "r"(dst), "l"(src))
#define CP_COMMIT() asm volatile("cp.async.commit_group;" ::: "memory")
#define CP_WAIT(n)  asm volatile("cp.async.wait_group %0;" :: "n"(n) : "memory")

__device__ __forceinline__ float fexp(float x) {
    const float L = 1.4426950408889634f;
    float t = fmaf(x, L, 12582912.0f);
    float n = t - 12582912.0f;
    float r = fmaf(x, L, -n);
    float u = r * 0.6931471805599453f;
    float p = 1.3888889e-3f;
    p = fmaf(p, u, 8.3333333e-3f);
    p = fmaf(p, u, 4.1666667e-2f);
    p = fmaf(p, u, 1.6666667e-1f);
    p = fmaf(p, u, 5.0e-1f);
    p = fmaf(p, u, 1.0f);
    p = fmaf(p, u, 1.0f);
    int e = (int)n;
    return __int_as_float((e + 127) << 23) * p;
}
__device__ __forceinline__ uint32_t pack_bf16x2(float a, float b) {
    __nv_bfloat162 pk = __floats2bfloat162_rn(a, b);
    return *(uint32_t*)&pk;
}

// ============ fused x cast + column sums (single read of x) =================
// grid (128, BATCH): blockIdx.x = 16-row chunk; thread owns 4 columns.
__global__ __launch_bounds__(256) void splitx_sumx_kernel(const float* __restrict__ x)
{
    const int b  = blockIdx.y;
    const int r0 = blockIdx.x * 16;
    const int d4 = threadIdx.x * 4;
    float s0 = 0, s1 = 0, s2 = 0, s3 = 0;
#pragma unroll 4
    for (int r = 0; r < 16; r++) {
        size_t idx = ((size_t)b * SEQ + r0 + r) * DIM + d4;
        float4 v = *(const float4*)(x + idx);
        __nv_bfloat16 h[4] = {
            __float2bfloat16(v.x), __float2bfloat16(v.y),
            __float2bfloat16(v.z), __float2bfloat16(v.w) };
        *(uint64_t*)&g_xh[idx] = *(const uint64_t*)h;
        s0 += v.x; s1 += v.y; s2 += v.z; s3 += v.w;
    }
    atomicAdd(&g_sx[b * DIM + d4 + 0], s0);
    atomicAdd(&g_sx[b * DIM + d4 + 1], s1);
    atomicAdd(&g_sx[b * DIM + d4 + 2], s2);
    atomicAdd(&g_sx[b * DIM + d4 + 3], s3);
}

// W cast; block 0 (all z copies, idempotent) zeroes g_sx for the fused kernel
__global__ __launch_bounds__(256) void split_w_kernel(
    const float* __restrict__ Wq, const float* __restrict__ Wk,
    const float* __restrict__ Wv)
{
    if (blockIdx.x == 0) {
        for (int i = threadIdx.x; i < BATCH * DIM; i += 256) g_sx[i] = 0.0f;
    }
    const int z = blockIdx.y;
    const float* W = (z == 0) ? Wq : (z == 1) ? Wk : Wv;
    int i = (blockIdx.x * 256 + threadIdx.x) * 4;
    float4 v = *(const float4*)(W + i);
    __nv_bfloat16 h[4] = {
        __float2bfloat16(v.x), __float2bfloat16(v.y),
        __float2bfloat16(v.z), __float2bfloat16(v.w) };
    *(uint64_t*)&g_wh[(size_t)z * DIM * DIM + i] = *(const uint64_t*)h;
}

// colsumV[b, n] = g_sx[b,:] . Wv[n,:] + 2048*bv[n]
__global__ __launch_bounds__(256) void colsumv_kernel(
    const float* __restrict__ Wv, const float* __restrict__ bv)
{
    const int wid  = threadIdx.x >> 5;
    const int lane = threadIdx.x & 31;
    const int gw   = blockIdx.x * 8 + wid;
    const int n    = gw & (DIM - 1);
    const int b    = gw >> 10;
    const float* wr = Wv + (size_t)n * DIM;
    const float* sx = g_sx + b * DIM;
    float acc = 0.0f;
#pragma unroll
    for (int it = 0; it < 8; it++) {
        int j = (it * 32 + lane) * 4;
        float4 w4 = *(const float4*)(wr + j);
        float4 s4 = *(const float4*)(sx + j);
        acc += w4.x * s4.x + w4.y * s4.y + w4.z * s4.z + w4.w * s4.w;
    }
#pragma unroll
    for (int o = 16; o > 0; o >>= 1)
        acc += __shfl_xor_sync(0xffffffffu, acc, o);
    if (lane == 0) {
        int h = n >> 6, w = n & 63;
        g_colsum[(b * NH + h) * HW + w] = acc + 2048.0f * bv[n];
    }
}

// ======================= QKV projection: 128x128 tiles, cp.async ============
#define ASTR 40

__global__ __launch_bounds__(256) void qkv_kernel(
    const float* __restrict__ bq, const float* __restrict__ bk,
    const float* __restrict__ bv)
{
    __shared__ __align__(16) unsigned short sA[2][128*ASTR];
    __shared__ __align__(16) unsigned short sB[2][128*ASTR];
    __shared__ float s_bias[128];

    const int t    = threadIdx.x;
    const int wid  = t >> 5;
    const int lane = t & 31;
    const int z    = blockIdx.z;
    const int n0   = blockIdx.x * 128;
    const int m0   = blockIdx.y * 128;

    const __nv_bfloat16* wofs = g_wh + (size_t)z * DIM * DIM;

    if (t < 128) {
        const float* bias = (z == 0) ? bq : (z == 1) ? bk : bv;
        s_bias[t] = bias[n0 + t];
    }

    const int wm = wid & 3;
    const int wn = wid >> 2;
    const int arow = t >> 2, aseg = t & 3;

    float d[2][8][4];
#pragma unroll
    for (int i = 0; i < 2; i++)
#pragma unroll
        for (int nf = 0; nf < 8; nf++)
#pragma unroll
            for (int r = 0; r < 4; r++) d[i][nf][r] = 0.0f;

#pragma unroll
    for (int i = 0; i < 2; i++) {
        int row = arow + i * 64;
        CP16(smem_u32(&sA[0][row * ASTR + aseg * 8]),
             &g_xh[(size_t)(m0 + row) * DIM + aseg * 8]);
        CP16(smem_u32(&sB[0][row * ASTR + aseg * 8]),
             &wofs[(size_t)(n0 + row) * DIM + aseg * 8]);
    }
    CP_COMMIT();

    for (int kc = 0; kc < 32; kc++) {
        if (kc < 31) {
            const int k0n = (kc + 1) * 32;
            const int bn  = (kc + 1) & 1;
#pragma unroll
            for (int i = 0; i < 2; i++) {
                int row = arow + i * 64;
                CP16(smem_u32(&sA[bn][row * ASTR + aseg * 8]),
                     &g_xh[(size_t)(m0 + row) * DIM + k0n + aseg * 8]);
                CP16(smem_u32(&sB[bn][row * ASTR + aseg * 8]),
                     &wofs[(size_t)(n0 + row) * DIM + k0n + aseg * 8]);
            }
            CP_COMMIT();
            CP_WAIT(1);
        } else {
            CP_WAIT(0);
        }
        __syncthreads();

        const uint32_t au = smem_u32(sA[kc & 1]);
        const uint32_t bu = smem_u32(sB[kc & 1]);
#pragma unroll
        for (int ks = 0; ks < 2; ks++) {
            uint32_t ah0[4], ah1[4];
            ldsm_x4(ah0, au + ((wm * 32 + (lane & 15)) * ASTR
                               + ks * 16 + (lane >> 4) * 8) * 2);
            ldsm_x4(ah1, au + ((wm * 32 + 16 + (lane & 15)) * ASTR
                               + ks * 16 + (lane >> 4) * 8) * 2);
#pragma unroll
            for (int nf = 0; nf < 8; nf++) {
                uint32_t b[2];
                ldsm_x2(b, bu + ((wn * 64 + nf * 8 + (lane & 7)) * ASTR
                                 + ks * 16 + (lane & 8)) * 2);
                mma_bf16(d[0][nf], ah0, b);
                mma_bf16(d[1][nf], ah1, b);
            }
        }
        __syncthreads();
    }

    const int h = (n0 >> 6) + wn;
    __nv_bfloat16* outp = (z == 0) ? g_qb : (z == 1) ? g_kb : g_vb;
#pragma unroll
    for (int i = 0; i < 2; i++) {
        int r = m0 + wm * 32 + i * 16 + (lane >> 2);
#pragma unroll
        for (int nf = 0; nf < 8; nf++) {
            int cl = nf * 8 + 2 * (lane & 3);
            float b0 = s_bias[wn * 64 + cl];
            float b1 = s_bias[wn * 64 + cl + 1];
            float v0 = d[i][nf][0] + b0;
            float v1 = d[i][nf][1] + b1;
            float v2 = d[i][nf][2] + b0;
            float v3 = d[i][nf][3] + b1;
#pragma unroll
            for (int half = 0; half < 2; half++) {
                int rr = r + half * 8;
                int b = rr >> 11, s = rr & (SEQ - 1);
                size_t o = ((size_t)((b * NH + h) * SEQ + s)) * HW + cl;
                *(__nv_bfloat162*)&outp[o] =
                    __floats2bfloat162_rn(half ? v2 : v0, half ? v3 : v1);
            }
        }
    }
}

// ============ single-pass fused attention via moment expansion ==============
// h = (colsum + M1/z + M2/(2z^2)) / (2049 + s2/(2z^2))
#define KVSTR   72
#define KVBYTES (128*KVSTR*2)
#define ESTR    136
#define OFF_K    0
#define OFF_V    (2*KVBYTES)                 // 36864
#define OFF_E    (4*KVBYTES)                 // 73728
#define OFF_E2   (OFF_E + 32*ESTR*2)         // 82432
#define OFF_Q    (OFF_E2 + 32*ESTR*2)        // 91136
#define OFF_CS   (OFF_Q + 32*KVSTR*2)        // 95744
#define OFF_Z    (OFF_CS + 256)              // 96000
#define OFF_S2   (OFF_Z + 128)               // 96128
#define ATTN_SMEM (OFF_S2 + 128)             // 96256

__global__ __launch_bounds__(256, 2) void attn_kernel(float* __restrict__ out)
{
    extern __shared__ char dsm[];
    char*  k_p  = dsm + OFF_K;
    char*  v_p  = dsm + OFF_V;
    char*  e_p  = dsm + OFF_E;
    char*  e2_p = dsm + OFF_E2;
    char*  q_p  = dsm + OFF_Q;
    float* s_cs = (float*)(dsm + OFF_CS);
    float* s_z  = (float*)(dsm + OFF_Z);
    float* s_s2 = (float*)(dsm + OFF_S2);

    const uint32_t k_u  = smem_u32(k_p);
    const uint32_t v_u  = smem_u32(v_p);
    const uint32_t e_u  = smem_u32(e_p);
    const uint32_t e2_u = smem_u32(e2_p);
    const uint32_t q_u  = smem_u32(q_p);

    const int t    = threadIdx.x;
    const int wid  = t >> 5;
    const int lane = t & 31;
    const int q0   = blockIdx.x * 32;
    const int bh   = blockIdx.y;

    const __nv_bfloat16* qg = g_qb + ((size_t)bh * SEQ + q0) * HW;
    const __nv_bfloat16* kg = g_kb + (size_t)bh * SEQ * HW;
    const __nv_bfloat16* vg = g_vb + (size_t)bh * SEQ * HW;

    const int wm   = wid & 1;
    const int wq   = wid >> 1;
    const int wm16 = wm * 16;
    const int erow = wm16 + (lane >> 2);
    const int m  = (wid >> 1) & 1;
    const int ch = wid >> 2;

    if (t < 32) { s_z[t] = 0.0f; s_s2[t] = 0.0f; }
    if (t < 64) s_cs[t] = g_colsum[bh * HW + t];
    {
        int row = t >> 3, seg = t & 7;
        *(uint4*)(q_p + (row * KVSTR + seg * 8) * 2) =
            *(const uint4*)(qg + row * HW + seg * 8);
    }
#pragma unroll
    for (int i = 0; i < 4; i++) {
        int idx = t + i * 256;
        int row = idx >> 3, seg = idx & 7;
        CP16(k_u + (row * KVSTR + seg * 8) * 2, kg + row * HW + seg * 8);
        CP16(v_u + (row * KVSTR + seg * 8) * 2, vg + row * HW + seg * 8);
    }
    CP_COMMIT();
    __syncthreads();

    uint32_t aq[4][4];
#pragma unroll
    for (int ks = 0; ks < 4; ks++) {
        uint32_t off = ((wm16 + (lane & 15)) * KVSTR + ks * 16 + (lane >> 4) * 8) * 2;
        ldsm_x4(aq[ks], q_u + off);
    }

    float zp0 = 0.f, zp1 = 0.f, sp0 = 0.f, sp1 = 0.f;
    float dd[4][4];
#pragma unroll
    for (int nf = 0; nf < 4; nf++)
#pragma unroll
        for (int r = 0; r < 4; r++) dd[nf][r] = 0.0f;

    for (int c = 0; c < 16; c++) {
        if (c < 15) {
            const __nv_bfloat16* ksrc = kg + (size_t)(c + 1) * 128 * HW;
            const __nv_bfloat16* vsrc = vg + (size_t)(c + 1) * 128 * HW;
            uint32_t kdst = k_u + ((c + 1) & 1) * KVBYTES;
            uint32_t vdst = v_u + ((c + 1) & 1) * KVBYTES;
#pragma unroll
            for (int i = 0; i < 4; i++) {
                int idx = t + i * 256;
                int row = idx >> 3, seg = idx & 7;
                CP16(kdst + (row * KVSTR + seg * 8) * 2, ksrc + row * HW + seg * 8);
                CP16(vdst + (row * KVSTR + seg * 8) * 2, vsrc + row * HW + seg * 8);
            }
            CP_COMMIT();
            CP_WAIT(1);
        } else {
            CP_WAIT(0);
        }
        __syncthreads();

        // ---- QK stage: e, e^2 for this 32x128 block (x4 ks-pair loads) ----
        const uint32_t kbuf = k_u + (c & 1) * KVBYTES;
#pragma unroll
        for (int nf = 0; nf < 4; nf++) {
            float d[4] = {0, 0, 0, 0};
#pragma unroll
            for (int ksp = 0; ksp < 4; ksp += 2) {
                uint32_t r[4];
                ldsm_x4(r, kbuf + ((wq * 32 + nf * 8 + (lane & 7)) * KVSTR
                                   + ksp * 16 + (lane & 8) + (lane >> 4) * 16) * 2);
                mma_bf16s(d, aq[ksp],     r[0], r[1]);
                mma_bf16s(d, aq[ksp + 1], r[2], r[3]);
            }
            float e0 = fexp(d[0] * 0.125f);
            float e1 = fexp(d[1] * 0.125f);
            float e2 = fexp(d[2] * 0.125f);
            float e3 = fexp(d[3] * 0.125f);
            float q0s = e0 * e0, q1s = e1 * e1, q2s = e2 * e2, q3s = e3 * e3;
            zp0 += e0 + e1;  zp1 += e2 + e3;
            sp0 += q0s + q1s; sp1 += q2s + q3s;
            int col = wq * 32 + nf * 8 + 2 * (lane & 3);
            *(uint32_t*)(e_p  + (erow * ESTR + col) * 2)       = pack_bf16x2(e0, e1);
            *(uint32_t*)(e_p  + ((erow + 8) * ESTR + col) * 2) = pack_bf16x2(e2, e3);
            *(uint32_t*)(e2_p + (erow * ESTR + col) * 2)       = pack_bf16x2(q0s, q1s);
            *(uint32_t*)(e2_p + ((erow + 8) * ESTR + col) * 2) = pack_bf16x2(q2s, q3s);
        }
        __syncthreads();

        // ---- PV stage: dd += (m ? e^2 : e) @ V  (x4t nf-pair loads) ----
        const uint32_t abuf = m ? e2_u : e_u;
        const uint32_t vbuf = v_u + (c & 1) * KVBYTES;
#pragma unroll
        for (int ks = 0; ks < 8; ks++) {
            uint32_t am[4];
            ldsm_x4(am, abuf + ((wm16 + (lane & 15)) * ESTR
                                + ks * 16 + (lane >> 4) * 8) * 2);
#pragma unroll
            for (int nfp = 0; nfp < 4; nfp += 2) {
                uint32_t r[4];
                ldsm_x4t(r, vbuf + ((ks * 16 + (lane & 7) + (lane & 8)) * KVSTR
                                    + ch * 32 + nfp * 8 + (lane >> 4) * 8) * 2);
                mma_bf16s(dd[nfp],     am, r[0], r[1]);
                mma_bf16s(dd[nfp + 1], am, r[2], r[3]);
            }
        }
    }

    // row sums: reduce lanes sharing a row, then across warps via atomics
    zp0 += __shfl_xor_sync(0xffffffffu, zp0, 1);
    zp0 += __shfl_xor_sync(0xffffffffu, zp0, 2);
    zp1 += __shfl_xor_sync(0xffffffffu, zp1, 1);
    zp1 += __shfl_xor_sync(0xffffffffu, zp1, 2);
    sp0 += __shfl_xor_sync(0xffffffffu, sp0, 1);
    sp0 += __shfl_xor_sync(0xffffffffu, sp0, 2);
    sp1 += __shfl_xor_sync(0xffffffffu, sp1, 1);
    sp1 += __shfl_xor_sync(0xffffffffu, sp1, 2);
    if ((lane & 3) == 0) {
        atomicAdd(&s_z[erow],      zp0);
        atomicAdd(&s_z[erow + 8],  zp1);
        atomicAdd(&s_s2[erow],     sp0);
        atomicAdd(&s_s2[erow + 8], sp1);
    }
    __syncthreads();

    // write M1 / M2 (fp32, 32x64) into e/e2 buffers (disjoint per warp)
    {
        float* Mb = (float*)(m ? e2_p : e_p);
        int r = wm16 + (lane >> 2);
#pragma unroll
        for (int nf = 0; nf < 4; nf++) {
            int col = ch * 32 + nf * 8 + 2 * (lane & 3);
            Mb[r * 64 + col]           = dd[nf][0];
            Mb[r * 64 + col + 1]       = dd[nf][1];
            Mb[(r + 8) * 64 + col]     = dd[nf][2];
            Mb[(r + 8) * 64 + col + 1] = dd[nf][3];
        }
    }
    __syncthreads();

    // epilogue: 256 threads cover 32 rows x 64 cols (8 floats each)
    {
        const float* M1 = (const float*)e_p;
        const float* M2 = (const float*)e2_p;
        const int b  = bh >> 4, hh = bh & 15;
        const int row = t >> 3;
        const int c0  = (t & 7) * 8;
        float z      = s_z[row];
        float invz   = 1.0f / z;
        float i2z2   = 0.5f * invz * invz;
        float den    = 1.0f / (2049.0f + s_s2[row] * i2z2);
        float* op = out + ((size_t)(b * SEQ + q0 + row)) * DIM + hh * HW + c0;
#pragma unroll
        for (int j = 0; j < 8; j += 4) {
            float4 m1 = *(const float4*)&M1[row * 64 + c0 + j];
            float4 m2 = *(const float4*)&M2[row * 64 + c0 + j];
            float4 cs = *(const float4*)&s_cs[c0 + j];
            float4 o;
            o.x = (cs.x + fmaf(m1.x, invz, m2.x * i2z2)) * den;
            o.y = (cs.y + fmaf(m1.y, invz, m2.y * i2z2)) * den;
            o.z = (cs.z + fmaf(m1.z, invz, m2.z * i2z2)) * den;
            o.w = (cs.w + fmaf(m1.w, invz, m2.w * i2z2)) * den;
            *(float4*)(op + j) = o;
        }
    }
}

// ---------------- launch -----------------------------------------------------
extern "C" void kernel_launch(void* const* d_in, const int* in_sizes, int n_in,
                              void* d_out, int out_size)
{
    const float* x  = (const float*)d_in[0];
    const float* Wq = (const float*)d_in[1];
    const float* bq = (const float*)d_in[2];
    const float* Wk = (const float*)d_in[3];
    const float* bk = (const float*)d_in[4];
    const float* Wv = (const float*)d_in[5];
    const float* bv = (const float*)d_in[6];
    float* out = (float*)d_out;

    // split_w first: it also zeroes g_sx for the fused x kernel
    {
        dim3 gw(DIM * DIM / 1024, 3);
        split_w_kernel<<<gw, 256>>>(Wq, Wk, Wv);
    }
    {
        dim3 gx(SEQ / 16, BATCH);
        splitx_sumx_kernel<<<gx, 256>>>(x);
    }
    colsumv_kernel<<<BATCH * DIM / 8, 256>>>(Wv, bv);
    {
        dim3 g(DIM / 128, MTOT / 128, 3);
        qkv_kernel<<<g, 256>>>(bq, bk, bv);
    }
    {
        cudaFuncSetAttribute(attn_kernel,
                             cudaFuncAttributeMaxDynamicSharedMemorySize, ATTN_SMEM);
        dim3 g2(SEQ / 32, BHTOT);
        attn_kernel<<<g2, 256, ATTN_SMEM>>>(out);
    }
}